// round 15
// baseline (speedup 1.0000x reference)
#include <cuda_runtime.h>
#include <cuda_fp16.h>
#include <cstdint>
#include <cstddef>

#define T_TOKENS 16384
#define D_MODEL  2048
#define N_EXP    8

// GEMM tiling
#define BM 128
#define BN 128
#define KC 64                        // fp16 elems per staged K-chunk
#define NCHUNK (D_MODEL / KC)        // 32
#define NT (D_MODEL / BN)            // 16 n-tiles

// Staged row: 64 fp16 = 128 B data + 16 B pad = 144 B -> conflict-free ldmatrix
#define STRIDE_B 144
#define A_OFF 0
#define B_OFF 18432
#define STAGE_BYTES 36864
#define NSTAGE 3
#define TILES_OFF 1024
#define SMEM_TOTAL (TILES_OFF + NSTAGE * STAGE_BYTES)   // 111616 -> 2 CTAs/SM

#define PREP_BLOCKS (T_TOKENS / 4)   // 4096
#define CONVW_BLOCKS 8192

// ---------------- device scratch ---------------------------------------------
__device__ int g_cnt[N_EXP];
__device__ int g_list[N_EXP][T_TOKENS];                       // packed token*2+slot
__device__ __half g_h [(size_t)T_TOKENS * D_MODEL];           // hidden fp16
__device__ __half g_w [(size_t)N_EXP * D_MODEL * D_MODEL];    // W fp16
__device__ float g_scr1[(size_t)T_TOKENS * D_MODEL];          // slot-1 outputs

// ---------------- helpers -----------------------------------------------------
__device__ __forceinline__ uint32_t smem_u32(const void* p) {
    uint32_t a;
    asm("{ .reg .u64 t; cvta.to.shared.u64 t, %1; cvt.u32.u64 %0, t; }" : "=r"(a) : "l"(p));
    return a;
}
__device__ __forceinline__ void cp16(uint32_t dst, const void* src, int sz) {
    asm volatile("cp.async.cg.shared.global [%0], [%1], 16, %2;"
                 :: "r"(dst), "l"(src), "r"(sz) : "memory");
}
__device__ __forceinline__ void cp_commit() {
    asm volatile("cp.async.commit_group;" ::: "memory");
}
__device__ __forceinline__ void ldsm4(uint32_t* r, uint32_t addr) {
    asm volatile("ldmatrix.sync.aligned.m8n8.x4.shared.b16 {%0,%1,%2,%3}, [%4];"
                 : "=r"(r[0]), "=r"(r[1]), "=r"(r[2]), "=r"(r[3]) : "r"(addr));
}
__device__ __forceinline__ void mma16816(float* d, const uint32_t* a, const uint32_t* b) {
    asm volatile(
        "mma.sync.aligned.m16n8k16.row.col.f32.f16.f16.f32 "
        "{%0,%1,%2,%3}, {%4,%5,%6,%7}, {%8,%9}, {%0,%1,%2,%3};"
        : "+f"(d[0]), "+f"(d[1]), "+f"(d[2]), "+f"(d[3])
        : "r"(a[0]), "r"(a[1]), "r"(a[2]), "r"(a[3]), "r"(b[0]), "r"(b[1]));
}
// named split-phase barriers (ids 1..3 = stage+1; count 512 = 256 arrive + 256 sync)
__device__ __forceinline__ void bar_arrive_id(int id) {
    asm volatile("bar.arrive %0, 512;" :: "r"(id));
}
__device__ __forceinline__ void bar_wait_id(int id) {
    asm volatile("bar.sync %0, 512;" :: "r"(id) : "memory");
}

// ---------------- kernel: zero routing counters -------------------------------
__global__ void init_kernel() {
    if (threadIdx.x < N_EXP) g_cnt[threadIdx.x] = 0;
}

// ---------------- kernel: fused (h convert + router) | W convert --------------
// blocks [0, PREP_BLOCKS)           : 4 tokens each -> g_h fp16 + routing lists
// blocks [PREP_BLOCKS, +CONVW_BLOCKS): grid-stride fp32 W -> fp16 g_w
__global__ __launch_bounds__(256) void prep_all_kernel(const float* __restrict__ h,
                                                       const float* __restrict__ Wg,
                                                       const float* __restrict__ bg,
                                                       const float* __restrict__ W) {
    __shared__ float sh[4 * D_MODEL];      // 32 KB
    __shared__ float slog[4][N_EXP];
    const int tid = threadIdx.x;

    if (blockIdx.x >= PREP_BLOCKS) {
        // ---- W convert path ----
        const long long n4 = (long long)N_EXP * D_MODEL * D_MODEL / 4;
        long long i = (long long)(blockIdx.x - PREP_BLOCKS) * 256 + tid;
        for (; i < n4; i += (long long)CONVW_BLOCKS * 256) {
            float4 v = reinterpret_cast<const float4*>(W)[i];
            __half2 p0 = __half2(__float2half_rn(v.x), __float2half_rn(v.y));
            __half2 p1 = __half2(__float2half_rn(v.z), __float2half_rn(v.w));
            reinterpret_cast<__half2*>(g_w)[i * 2 + 0] = p0;
            reinterpret_cast<__half2*>(g_w)[i * 2 + 1] = p1;
        }
        return;
    }

    // ---- h convert + router path ----
    const int t0 = blockIdx.x * 4;
    const size_t base = (size_t)t0 * D_MODEL;

    for (int i = tid * 4; i < 4 * D_MODEL; i += 256 * 4)
        *reinterpret_cast<float4*>(sh + i) =
            *reinterpret_cast<const float4*>(h + base + i);
    __syncthreads();

    for (int i = tid * 4; i < 4 * D_MODEL; i += 256 * 4) {
        float4 v = *reinterpret_cast<const float4*>(sh + i);
        __half2 p0 = __half2(__float2half_rn(v.x), __float2half_rn(v.y));
        __half2 p1 = __half2(__float2half_rn(v.z), __float2half_rn(v.w));
        *reinterpret_cast<__half2*>(g_h + base + i)     = p0;
        *reinterpret_cast<__half2*>(g_h + base + i + 2) = p1;
    }

    const int w = tid >> 5, lane = tid & 31;
    float wreg[64];
    #pragma unroll
    for (int j = 0; j < 64; j++) wreg[j] = Wg[w * D_MODEL + lane + j * 32];

    #pragma unroll
    for (int tk = 0; tk < 4; tk++) {
        float s = 0.f;
        #pragma unroll
        for (int j = 0; j < 64; j++) s += sh[tk * D_MODEL + lane + j * 32] * wreg[j];
        #pragma unroll
        for (int o = 16; o > 0; o >>= 1) s += __shfl_xor_sync(0xffffffffu, s, o);
        if (lane == 0) slog[tk][w] = s + bg[w];
    }
    __syncthreads();

    if (tid < 4) {
        const int token = t0 + tid;
        int b0 = 0; float v0 = slog[tid][0];
        #pragma unroll
        for (int i = 1; i < N_EXP; i++) if (slog[tid][i] > v0) { v0 = slog[tid][i]; b0 = i; }
        int b1 = -1; float v1 = -3.402823466e38f;
        #pragma unroll
        for (int i = 0; i < N_EXP; i++)
            if (i != b0 && slog[tid][i] > v1) { v1 = slog[tid][i]; b1 = i; }
        int p0 = atomicAdd(&g_cnt[b0], 1); g_list[b0][p0] = token * 2;       // -> out
        int p1 = atomicAdd(&g_cnt[b1], 1); g_list[b1][p1] = token * 2 + 1;   // -> scr1
    }
}

// ---------------- kernel: grouped GEMM, fp16 x fp16 -> fp32 -------------------
// grid.x = ntile (16), grid.y = e*128 + mtile. 256 threads = 8 warps (4m x 2n).
// Warp tile 32x64, m16n8k16. KC=64, 3-stage cp.async, 2 CTAs/SM.
// Split-phase stage-reuse guard: bar.arrive after MMAs, bar.sync before reuse.
__global__ __launch_bounds__(256, 2)
void moe_mma_gemm(const float* __restrict__ bias, float* __restrict__ out) {
    extern __shared__ char smem[];
    const uint32_t sb = smem_u32(smem);
    int* rowid = reinterpret_cast<int*>(smem);
    const int tid = threadIdx.x;
    const int ntile = blockIdx.x;
    const int et = blockIdx.y;
    const int e = et >> 7;
    const int mtile = et & 127;
    const int cnt = g_cnt[e];
    const int m0 = mtile * BM;
    if (m0 >= cnt) return;

    if (tid < BM) rowid[tid] = (m0 + tid < cnt) ? g_list[e][m0 + tid] : -1;
    __syncthreads();

    const __half* Wb = g_w + ((size_t)e * D_MODEL + (size_t)ntile * BN) * D_MODEL;

    // ---- precompute per-thread staging pointers (loop-invariant) -----------
    const char* asrc[4]; int asz[4];
    const char* bsrc[4];
    uint32_t doff[4];
    #pragma unroll
    for (int i = 0; i < 4; i++) {
        const int u = tid + i * 256;              // 0..1023
        const int row = u >> 3, cc = u & 7;
        doff[i] = (uint32_t)(row * STRIDE_B + cc * 16);
        const int sv = rowid[row];
        asz[i] = (sv >= 0) ? 16 : 0;
        asrc[i] = reinterpret_cast<const char*>(
            g_h + (size_t)((sv >= 0) ? (sv >> 1) : 0) * D_MODEL + cc * 8);
        bsrc[i] = reinterpret_cast<const char*>(Wb + (size_t)row * D_MODEL + cc * 8);
    }

    auto stage_load = [&](int st, int c) {
        const uint32_t base = sb + TILES_OFF + st * STAGE_BYTES;
        const size_t kadv = (size_t)c * (KC * 2);     // bytes along K
        #pragma unroll
        for (int i = 0; i < 4; i++) {
            cp16(base + A_OFF + doff[i], asrc[i] + kadv, asz[i]);
            cp16(base + B_OFF + doff[i], bsrc[i] + kadv, 16);
        }
        cp_commit();
    };

    const int lane = tid & 31, wid = tid >> 5;
    const int wm = wid & 3;                     // 4 warps over 128 rows
    const int wn = wid >> 2;                    // 2 warps over 128 cols
    const uint32_t arow = (uint32_t)((wm * 32 + (lane & 15)) * STRIDE_B + (lane >> 4) * 16);
    const uint32_t brow = (uint32_t)((wn * 64 + (lane & 15)) * STRIDE_B + (lane >> 4) * 16);

    float acc[2][8][4];
    #pragma unroll
    for (int mf = 0; mf < 2; mf++)
        #pragma unroll
        for (int n8 = 0; n8 < 8; n8++)
            #pragma unroll
            for (int q = 0; q < 4; q++) acc[mf][n8][q] = 0.f;

    stage_load(0, 0);
    stage_load(1, 1);
    bar_arrive_id(3);                           // seed reuse-guard for stage 2

    int st = 0;
    for (int c = 0; c < NCHUNK; c++) {
        if (c + 2 < NCHUNK) {
            const int ws = (st + 2) % NSTAGE;
            bar_wait_id(ws + 1);                // prior readers of ws are done
            stage_load(ws, c + 2);
            asm volatile("cp.async.wait_group 2;" ::: "memory");
        } else if (c + 1 < NCHUNK) {
            asm volatile("cp.async.wait_group 1;" ::: "memory");
        } else {
            asm volatile("cp.async.wait_group 0;" ::: "memory");
        }
        __syncthreads();                        // stage st data visible to all

        const uint32_t stb = sb + TILES_OFF + st * STAGE_BYTES;
        #pragma unroll
        for (int ks = 0; ks < 4; ks++) {
            const uint32_t koff = ks * 32;      // 16 fp16 = 32 B
            uint32_t aa[2][4];
            #pragma unroll
            for (int mf = 0; mf < 2; mf++)
                ldsm4(aa[mf], stb + A_OFF + arow + mf * (16 * STRIDE_B) + koff);
            uint32_t bb[8][2];
            #pragma unroll
            for (int nf = 0; nf < 4; nf++) {
                uint32_t r[4];
                ldsm4(r, stb + B_OFF + brow + nf * (16 * STRIDE_B) + koff);
                bb[nf * 2 + 0][0] = r[0]; bb[nf * 2 + 0][1] = r[2];
                bb[nf * 2 + 1][0] = r[1]; bb[nf * 2 + 1][1] = r[3];
            }
            #pragma unroll
            for (int mf = 0; mf < 2; mf++)
                #pragma unroll
                for (int n8 = 0; n8 < 8; n8++)
                    mma16816(acc[mf][n8], aa[mf], bb[n8]);
        }
        bar_arrive_id(st + 1);                  // this thread done reading st
        st = (st + 1) % NSTAGE;
    }

    // ---- epilogue: + bias, scatter rows to out (slot 0) / scr1 (slot 1) ----
    const int quad = lane >> 2, tq = lane & 3;
    #pragma unroll
    for (int mf = 0; mf < 2; mf++) {
        #pragma unroll
        for (int half = 0; half < 2; half++) {
            const int mrow = wm * 32 + mf * 16 + half * 8 + quad;
            const int sv = rowid[mrow];
            if (sv < 0) continue;
            float* dst = ((sv & 1) ? g_scr1 : out) + (size_t)(sv >> 1) * D_MODEL;
            #pragma unroll
            for (int n8 = 0; n8 < 8; n8++) {
                const int gcol = ntile * BN + wn * 64 + n8 * 8 + tq * 2;
                const float* bp = bias + e * D_MODEL + gcol;
                float2 o;
                o.x = acc[mf][n8][half * 2 + 0] + bp[0];
                o.y = acc[mf][n8][half * 2 + 1] + bp[1];
                *reinterpret_cast<float2*>(dst + gcol) = o;
            }
        }
    }
}

// ---------------- kernel: combine (out[t] += scr1[t]) -------------------------
__global__ void combine_kernel(float* __restrict__ out) {
    const long long n4 = (long long)T_TOKENS * D_MODEL / 4;
    const float4* s4 = reinterpret_cast<const float4*>(g_scr1);
    float4* o4 = reinterpret_cast<float4*>(out);
    for (long long i = (long long)blockIdx.x * blockDim.x + threadIdx.x; i < n4;
         i += (long long)gridDim.x * blockDim.x) {
        float4 a = o4[i];
        float4 b = s4[i];
        o4[i] = make_float4(a.x + b.x, a.y + b.y, a.z + b.z, a.w + b.w);
    }
}

// ---------------- launch ------------------------------------------------------
extern "C" void kernel_launch(void* const* d_in, const int* in_sizes, int n_in,
                              void* d_out, int out_size) {
    const float* h  = (const float*)d_in[0];   // [16384, 2048]
    const float* Wg = (const float*)d_in[1];   // [8, 2048]
    const float* bg = (const float*)d_in[2];   // [8]
    const float* W  = (const float*)d_in[3];   // [8, 2048, 2048]
    const float* b  = (const float*)d_in[4];   // [8, 2048]
    float* out = (float*)d_out;                // [16384, 2048]
    (void)in_sizes; (void)n_in; (void)out_size;

    init_kernel<<<1, 32>>>();

    prep_all_kernel<<<PREP_BLOCKS + CONVW_BLOCKS, 256>>>(h, Wg, bg, W);

    cudaFuncSetAttribute(moe_mma_gemm, cudaFuncAttributeMaxDynamicSharedMemorySize, SMEM_TOTAL);
    dim3 grid(NT, N_EXP * (T_TOKENS / BM));
    moe_mma_gemm<<<grid, 256, SMEM_TOTAL>>>(b, out);

    combine_kernel<<<1024, 256>>>(out);
}

// round 17
// speedup vs baseline: 1.0615x; 1.0615x over previous
#include <cuda_runtime.h>
#include <cuda_fp16.h>
#include <cstdint>
#include <cstddef>

#define T_TOKENS 16384
#define D_MODEL  2048
#define N_EXP    8

// GEMM tiling
#define BM 128
#define BN 128
#define KC 64                        // fp16 elems per staged K-chunk
#define NCHUNK (D_MODEL / KC)        // 32
#define NT (D_MODEL / BN)            // 16 n-tiles

// Staged row: 64 fp16 = 128 B data + 16 B pad = 144 B -> conflict-free ldmatrix
#define STRIDE_B 144
#define A_OFF 0
#define B_OFF 18432
#define STAGE_BYTES 36864
#define NSTAGE 3
#define TILES_OFF 1024
#define SMEM_TOTAL (TILES_OFF + NSTAGE * STAGE_BYTES)   // 111616 -> 2 CTAs/SM

#define PREP_BLOCKS (T_TOKENS / 4)   // 4096
#define CONVW_BLOCKS 8192
#define ZERO_BLOCKS 2048

// ---------------- device scratch ---------------------------------------------
__device__ int g_cnt[N_EXP];
__device__ int g_list[N_EXP][T_TOKENS];                       // packed token*2+slot
__device__ __half g_h [(size_t)T_TOKENS * D_MODEL];           // hidden fp16
__device__ __half g_w [(size_t)N_EXP * D_MODEL * D_MODEL];    // W fp16

// ---------------- helpers -----------------------------------------------------
__device__ __forceinline__ uint32_t smem_u32(const void* p) {
    uint32_t a;
    asm("{ .reg .u64 t; cvta.to.shared.u64 t, %1; cvt.u32.u64 %0, t; }" : "=r"(a) : "l"(p));
    return a;
}
__device__ __forceinline__ void cp16(uint32_t dst, const void* src, int sz) {
    asm volatile("cp.async.cg.shared.global [%0], [%1], 16, %2;"
                 :: "r"(dst), "l"(src), "r"(sz) : "memory");
}
__device__ __forceinline__ void cp_commit() {
    asm volatile("cp.async.commit_group;" ::: "memory");
}
__device__ __forceinline__ void ldsm4(uint32_t* r, uint32_t addr) {
    asm volatile("ldmatrix.sync.aligned.m8n8.x4.shared.b16 {%0,%1,%2,%3}, [%4];"
                 : "=r"(r[0]), "=r"(r[1]), "=r"(r[2]), "=r"(r[3]) : "r"(addr));
}
__device__ __forceinline__ void mma16816(float* d, const uint32_t* a, const uint32_t* b) {
    asm volatile(
        "mma.sync.aligned.m16n8k16.row.col.f32.f16.f16.f32 "
        "{%0,%1,%2,%3}, {%4,%5,%6,%7}, {%8,%9}, {%0,%1,%2,%3};"
        : "+f"(d[0]), "+f"(d[1]), "+f"(d[2]), "+f"(d[3])
        : "r"(a[0]), "r"(a[1]), "r"(a[2]), "r"(a[3]), "r"(b[0]), "r"(b[1]));
}
__device__ __forceinline__ void red_add_v2(float* addr, float x, float y) {
    asm volatile("red.global.add.v2.f32 [%0], {%1, %2};"
                 :: "l"(addr), "f"(x), "f"(y) : "memory");
}

// ---------------- kernel: zero routing counters -------------------------------
__global__ void init_kernel() {
    if (threadIdx.x < N_EXP) g_cnt[threadIdx.x] = 0;
}

// ---------------- kernel: (h convert + router) | W convert | zero out ---------
// blocks [0, PREP_BLOCKS)                       : 4 tokens -> g_h fp16 + routing
// blocks [PREP_BLOCKS, +CONVW_BLOCKS)           : fp32 W -> fp16 g_w
// blocks [PREP_BLOCKS+CONVW_BLOCKS, +ZERO_BLOCKS): zero out (RED target)
__global__ __launch_bounds__(256) void prep_all_kernel(const float* __restrict__ h,
                                                       const float* __restrict__ Wg,
                                                       const float* __restrict__ bg,
                                                       const float* __restrict__ W,
                                                       float* __restrict__ out) {
    __shared__ float sh[4 * D_MODEL];      // 32 KB
    __shared__ float slog[4][N_EXP];
    const int tid = threadIdx.x;

    if (blockIdx.x >= PREP_BLOCKS + CONVW_BLOCKS) {
        // ---- zero-out path ----
        const long long n4 = (long long)T_TOKENS * D_MODEL / 4;
        long long i = (long long)(blockIdx.x - PREP_BLOCKS - CONVW_BLOCKS) * 256 + tid;
        float4 z = make_float4(0.f, 0.f, 0.f, 0.f);
        for (; i < n4; i += (long long)ZERO_BLOCKS * 256)
            reinterpret_cast<float4*>(out)[i] = z;
        return;
    }
    if (blockIdx.x >= PREP_BLOCKS) {
        // ---- W convert path ----
        const long long n4 = (long long)N_EXP * D_MODEL * D_MODEL / 4;
        long long i = (long long)(blockIdx.x - PREP_BLOCKS) * 256 + tid;
        for (; i < n4; i += (long long)CONVW_BLOCKS * 256) {
            float4 v = reinterpret_cast<const float4*>(W)[i];
            __half2 p0 = __half2(__float2half_rn(v.x), __float2half_rn(v.y));
            __half2 p1 = __half2(__float2half_rn(v.z), __float2half_rn(v.w));
            reinterpret_cast<__half2*>(g_w)[i * 2 + 0] = p0;
            reinterpret_cast<__half2*>(g_w)[i * 2 + 1] = p1;
        }
        return;
    }

    // ---- h convert + router path ----
    const int t0 = blockIdx.x * 4;
    const size_t base = (size_t)t0 * D_MODEL;

    for (int i = tid * 4; i < 4 * D_MODEL; i += 256 * 4)
        *reinterpret_cast<float4*>(sh + i) =
            *reinterpret_cast<const float4*>(h + base + i);
    __syncthreads();

    for (int i = tid * 4; i < 4 * D_MODEL; i += 256 * 4) {
        float4 v = *reinterpret_cast<const float4*>(sh + i);
        __half2 p0 = __half2(__float2half_rn(v.x), __float2half_rn(v.y));
        __half2 p1 = __half2(__float2half_rn(v.z), __float2half_rn(v.w));
        *reinterpret_cast<__half2*>(g_h + base + i)     = p0;
        *reinterpret_cast<__half2*>(g_h + base + i + 2) = p1;
    }

    const int w = tid >> 5, lane = tid & 31;
    float wreg[64];
    #pragma unroll
    for (int j = 0; j < 64; j++) wreg[j] = Wg[w * D_MODEL + lane + j * 32];

    #pragma unroll
    for (int tk = 0; tk < 4; tk++) {
        float s = 0.f;
        #pragma unroll
        for (int j = 0; j < 64; j++) s += sh[tk * D_MODEL + lane + j * 32] * wreg[j];
        #pragma unroll
        for (int o = 16; o > 0; o >>= 1) s += __shfl_xor_sync(0xffffffffu, s, o);
        if (lane == 0) slog[tk][w] = s + bg[w];
    }
    __syncthreads();

    if (tid < 4) {
        const int token = t0 + tid;
        int b0 = 0; float v0 = slog[tid][0];
        #pragma unroll
        for (int i = 1; i < N_EXP; i++) if (slog[tid][i] > v0) { v0 = slog[tid][i]; b0 = i; }
        int b1 = -1; float v1 = -3.402823466e38f;
        #pragma unroll
        for (int i = 0; i < N_EXP; i++)
            if (i != b0 && slog[tid][i] > v1) { v1 = slog[tid][i]; b1 = i; }
        int p0 = atomicAdd(&g_cnt[b0], 1); g_list[b0][p0] = token * 2;
        int p1 = atomicAdd(&g_cnt[b1], 1); g_list[b1][p1] = token * 2 + 1;
    }
}

// ---------------- kernel: grouped GEMM, fp16 x fp16 -> fp32 -------------------
// grid.x = ntile (16), grid.y = e*128 + mtile. 256 threads = 8 warps (4m x 2n).
// Warp tile 32x64, m16n8k16. KC=64, 3-stage cp.async, 2 CTAs/SM.
// Epilogue: red.global.add.v2 into zeroed out for BOTH slots (order-invariant).
__global__ __launch_bounds__(256, 2)
void moe_mma_gemm(const float* __restrict__ bias, float* __restrict__ out) {
    extern __shared__ char smem[];
    const uint32_t sb = smem_u32(smem);
    int* rowid = reinterpret_cast<int*>(smem);
    const int tid = threadIdx.x;
    const int ntile = blockIdx.x;
    const int et = blockIdx.y;
    const int e = et >> 7;
    const int mtile = et & 127;
    const int cnt = g_cnt[e];
    const int m0 = mtile * BM;
    if (m0 >= cnt) return;

    if (tid < BM) rowid[tid] = (m0 + tid < cnt) ? g_list[e][m0 + tid] : -1;
    __syncthreads();

    const __half* Wb = g_w + ((size_t)e * D_MODEL + (size_t)ntile * BN) * D_MODEL;

    // ---- precompute per-thread staging pointers (loop-invariant) -----------
    const char* asrc[4]; int asz[4];
    const char* bsrc[4];
    uint32_t doff[4];
    #pragma unroll
    for (int i = 0; i < 4; i++) {
        const int u = tid + i * 256;              // 0..1023
        const int row = u >> 3, cc = u & 7;
        doff[i] = (uint32_t)(row * STRIDE_B + cc * 16);
        const int sv = rowid[row];
        asz[i] = (sv >= 0) ? 16 : 0;
        asrc[i] = reinterpret_cast<const char*>(
            g_h + (size_t)((sv >= 0) ? (sv >> 1) : 0) * D_MODEL + cc * 8);
        bsrc[i] = reinterpret_cast<const char*>(Wb + (size_t)row * D_MODEL + cc * 8);
    }
    __syncthreads();

    auto stage_load = [&](int st, int c) {
        const uint32_t base = sb + TILES_OFF + st * STAGE_BYTES;
        const size_t kadv = (size_t)c * (KC * 2);     // bytes along K
        #pragma unroll
        for (int i = 0; i < 4; i++) {
            cp16(base + A_OFF + doff[i], asrc[i] + kadv, asz[i]);
            cp16(base + B_OFF + doff[i], bsrc[i] + kadv, 16);
        }
        cp_commit();
    };

    const int lane = tid & 31, wid = tid >> 5;
    const int wm = wid & 3;                     // 4 warps over 128 rows
    const int wn = wid >> 2;                    // 2 warps over 128 cols
    const uint32_t arow = (uint32_t)((wm * 32 + (lane & 15)) * STRIDE_B + (lane >> 4) * 16);
    const uint32_t brow = (uint32_t)((wn * 64 + (lane & 15)) * STRIDE_B + (lane >> 4) * 16);

    float acc[2][8][4];
    #pragma unroll
    for (int mf = 0; mf < 2; mf++)
        #pragma unroll
        for (int n8 = 0; n8 < 8; n8++)
            #pragma unroll
            for (int q = 0; q < 4; q++) acc[mf][n8][q] = 0.f;

    stage_load(0, 0);
    stage_load(1, 1);

    int st = 0;
    for (int c = 0; c < NCHUNK; c++) {
        if (c + 2 < NCHUNK) {
            stage_load((st + 2) % NSTAGE, c + 2);
            asm volatile("cp.async.wait_group 2;" ::: "memory");
        } else if (c + 1 < NCHUNK) {
            asm volatile("cp.async.wait_group 1;" ::: "memory");
        } else {
            asm volatile("cp.async.wait_group 0;" ::: "memory");
        }
        __syncthreads();

        const uint32_t stb = sb + TILES_OFF + st * STAGE_BYTES;
        #pragma unroll
        for (int ks = 0; ks < 4; ks++) {
            const uint32_t koff = ks * 32;      // 16 fp16 = 32 B
            uint32_t aa[2][4];
            #pragma unroll
            for (int mf = 0; mf < 2; mf++)
                ldsm4(aa[mf], stb + A_OFF + arow + mf * (16 * STRIDE_B) + koff);
            uint32_t bb[8][2];
            #pragma unroll
            for (int nf = 0; nf < 4; nf++) {
                uint32_t r[4];
                ldsm4(r, stb + B_OFF + brow + nf * (16 * STRIDE_B) + koff);
                bb[nf * 2 + 0][0] = r[0]; bb[nf * 2 + 0][1] = r[2];
                bb[nf * 2 + 1][0] = r[1]; bb[nf * 2 + 1][1] = r[3];
            }
            #pragma unroll
            for (int mf = 0; mf < 2; mf++)
                #pragma unroll
                for (int n8 = 0; n8 < 8; n8++)
                    mma16816(acc[mf][n8], aa[mf], bb[n8]);
        }
        __syncthreads();
        st = (st + 1) % NSTAGE;
    }

    // ---- epilogue: + bias, RED-accumulate rows into out (both slots) -------
    const int quad = lane >> 2, tq = lane & 3;
    #pragma unroll
    for (int mf = 0; mf < 2; mf++) {
        #pragma unroll
        for (int half = 0; half < 2; half++) {
            const int mrow = wm * 32 + mf * 16 + half * 8 + quad;
            const int sv = rowid[mrow];
            if (sv < 0) continue;
            float* dst = out + (size_t)(sv >> 1) * D_MODEL;
            #pragma unroll
            for (int n8 = 0; n8 < 8; n8++) {
                const int gcol = ntile * BN + wn * 64 + n8 * 8 + tq * 2;
                const float* bp = bias + e * D_MODEL + gcol;
                red_add_v2(dst + gcol,
                           acc[mf][n8][half * 2 + 0] + bp[0],
                           acc[mf][n8][half * 2 + 1] + bp[1]);
            }
        }
    }
}

// ---------------- launch ------------------------------------------------------
extern "C" void kernel_launch(void* const* d_in, const int* in_sizes, int n_in,
                              void* d_out, int out_size) {
    const float* h  = (const float*)d_in[0];   // [16384, 2048]
    const float* Wg = (const float*)d_in[1];   // [8, 2048]
    const float* bg = (const float*)d_in[2];   // [8]
    const float* W  = (const float*)d_in[3];   // [8, 2048, 2048]
    const float* b  = (const float*)d_in[4];   // [8, 2048]
    float* out = (float*)d_out;                // [16384, 2048]
    (void)in_sizes; (void)n_in; (void)out_size;

    init_kernel<<<1, 32>>>();

    prep_all_kernel<<<PREP_BLOCKS + CONVW_BLOCKS + ZERO_BLOCKS, 256>>>(h, Wg, bg, W, out);

    cudaFuncSetAttribute(moe_mma_gemm, cudaFuncAttributeMaxDynamicSharedMemorySize, SMEM_TOTAL);
    dim3 grid(NT, N_EXP * (T_TOKENS / BM));
    moe_mma_gemm<<<grid, 256, SMEM_TOTAL>>>(b, out);
}